// round 14
// baseline (speedup 1.0000x reference)
#include <cuda_runtime.h>
#include <cuda_bf16.h>
#include <cstdint>

#define Bb   8
#define Nn   4096
#define Mm   2048
#define DIN  256
#define DOUT 128

__device__ __nv_bfloat16 g_Qh [Bb*Mm*DOUT];
__device__ __nv_bfloat16 g_Ql [Bb*Mm*DOUT];
__device__ __nv_bfloat16 g_Kh [Bb*Mm*DOUT];
__device__ __nv_bfloat16 g_Kl [Bb*Mm*DOUT];
__device__ float         g_V  [Bb*Mm*DOUT];
__device__ __nv_bfloat16 g_Vth[Bb*DOUT*Mm];    // [b][e][m]
__device__ __nv_bfloat16 g_Vtl[Bb*DOUT*Mm];
__device__ __nv_bfloat16 g_Wth[3*DOUT*DIN];    // [wsel][n][k]
__device__ __nv_bfloat16 g_Wtl[3*DOUT*DIN];

// ---------------- helpers ----------------
__device__ __forceinline__ uint32_t cvta_smem(const void* p) {
    uint32_t a;
    asm("{ .reg .u64 t; cvta.to.shared.u64 t, %1; cvt.u32.u64 %0, t; }" : "=r"(a) : "l"(p));
    return a;
}
__device__ __forceinline__ uint32_t b2pack(float a, float b) {
    uint16_t la = __bfloat16_as_ushort(__float2bfloat16(a));
    uint16_t lb = __bfloat16_as_ushort(__float2bfloat16(b));
    return (uint32_t)la | ((uint32_t)lb << 16);
}
__device__ __forceinline__ float bhi(float x) {
    return __bfloat162float(__float2bfloat16(x));
}
__device__ __forceinline__ void ldmA(uint32_t a[4], uint32_t addr) {
    asm volatile("ldmatrix.sync.aligned.m8n8.x4.shared.b16 {%0,%1,%2,%3}, [%4];"
        : "=r"(a[0]),"=r"(a[1]),"=r"(a[2]),"=r"(a[3]) : "r"(addr));
}
__device__ __forceinline__ void ldmB4(uint32_t b[4], uint32_t addr) {
    asm volatile("ldmatrix.sync.aligned.m8n8.x4.shared.b16 {%0,%1,%2,%3}, [%4];"
        : "=r"(b[0]),"=r"(b[1]),"=r"(b[2]),"=r"(b[3]) : "r"(addr));
}
__device__ __forceinline__ void mma16816(float c[4], const uint32_t a[4], const uint32_t b[2]) {
    asm volatile("mma.sync.aligned.m16n8k16.row.col.f32.bf16.bf16.f32 "
        "{%0,%1,%2,%3}, {%4,%5,%6,%7}, {%8,%9}, {%0,%1,%2,%3};"
        : "+f"(c[0]),"+f"(c[1]),"+f"(c[2]),"+f"(c[3])
        : "r"(a[0]),"r"(a[1]),"r"(a[2]),"r"(a[3]), "r"(b[0]),"r"(b[1]));
}
#define CPA(d, s) asm volatile("cp.async.cg.shared.global [%0], [%1], 16;" :: "r"(d), "l"(s))
#define CPC()     asm volatile("cp.async.commit_group;" ::: "memory")
#define CPW1()    asm volatile("cp.async.wait_group 1;" ::: "memory")
#define CPW0()    asm volatile("cp.async.wait_group 0;" ::: "memory")

#define PIT 136
#define PITB 272
#define P64B 144

// ---------------------------------------------------------------------------
// prep: 48 blocks (round-13 proven).
// ---------------------------------------------------------------------------
__global__ void prep_kernel(const float* __restrict__ Wq,
                            const float* __restrict__ Wk,
                            const float* __restrict__ Wv)
{
    const int wsel  = blockIdx.x >> 4;
    const int slice = blockIdx.x & 15;
    const float* W = (wsel == 0) ? Wq : (wsel == 1) ? Wk : Wv;
    __nv_bfloat16* dh = g_Wth + wsel * DOUT * DIN;
    __nv_bfloat16* dl = g_Wtl + wsel * DOUT * DIN;
    const int n0 = slice * 8;
    for (int i = threadIdx.x; i < 8 * (DIN/2); i += 256) {
        int n = n0 + (i >> 7), k = (i & 127) * 2;
        float x0 = W[(size_t)k*DOUT + n];
        float x1 = W[(size_t)(k+1)*DOUT + n];
        *reinterpret_cast<uint32_t*>(dh + (size_t)n*DIN + k) = b2pack(x0, x1);
        *reinterpret_cast<uint32_t*>(dl + (size_t)n*DIN + k) =
            b2pack(x0 - bhi(x0), x1 - bhi(x1));
    }
}

// ---------------------------------------------------------------------------
// projmma (round-9 proven, frozen): 256 threads, 8 warps (4m x 2n).
// ---------------------------------------------------------------------------
__global__ __launch_bounds__(256, 1)
void projmma_kernel(const float* __restrict__ Y, const int* __restrict__ idx,
                    const float* __restrict__ bq, const float* __restrict__ bk,
                    const float* __restrict__ bv)
{
    extern __shared__ char smraw[];
    char* Ah = smraw;
    char* Al = smraw + 69632;
    char* Bh = smraw + 139264;
    char* Bl = smraw + 174080;
    float* Vs = reinterpret_cast<float*>(Bh);
    __shared__ int idxs[128];

    const int tid = threadIdx.x, lane = tid & 31, wid = tid >> 5;
    const int wm = wid >> 1, wn = wid & 1;
    const int row0 = blockIdx.x * 128;
    const int b    = row0 / Mm;
    const int m0   = row0 % Mm;

    if (tid < 128) idxs[tid] = idx[b*Mm + m0 + tid];
    __syncthreads();

    for (int i = tid; i < 128*64; i += 256) {
        int row = i >> 6, c4 = i & 63;
        float4 y = *reinterpret_cast<const float4*>(
            Y + ((size_t)b*Nn + idxs[row])*DIN + c4*4);
        int kc = c4 >> 5;
        uint32_t off = (uint32_t)(kc*34816 + row*PITB + (c4 & 31)*8);
        *reinterpret_cast<uint2*>(Ah + off) =
            make_uint2(b2pack(y.x, y.y), b2pack(y.z, y.w));
        *reinterpret_cast<uint2*>(Al + off) =
            make_uint2(b2pack(y.x-bhi(y.x), y.y-bhi(y.y)),
                       b2pack(y.z-bhi(y.z), y.w-bhi(y.w)));
    }

    const uint32_t sAh = cvta_smem(Ah), sAl = cvta_smem(Al);
    const uint32_t sBh = cvta_smem(Bh), sBl = cvta_smem(Bl);

    const int aRow  = wm*32 + (lane & 15);
    const int aKb   = (lane >> 4) * 8;
    const int bRow4 = wn*64 + ((lane >> 4) << 3) + (lane & 7);
    const int bK4   = ((lane >> 3) & 1) * 8;

    #pragma unroll 1
    for (int wsel = 0; wsel < 3; wsel++) {
        float acc[2][8][4] = {};
        #pragma unroll 1
        for (int kc = 0; kc < 2; kc++) {
            __syncthreads();
            const __nv_bfloat16* wh = g_Wth + (size_t)wsel*DOUT*DIN + kc*128;
            const __nv_bfloat16* wl = g_Wtl + (size_t)wsel*DOUT*DIN + kc*128;
            for (int i = tid; i < 128*16; i += 256) {
                int n = i >> 4, c8 = i & 15;
                uint32_t off = (uint32_t)(n*PITB + c8*16);
                size_t go = (size_t)n*DIN + c8*8;
                *reinterpret_cast<uint4*>(Bh + off) =
                    *reinterpret_cast<const uint4*>(wh + go);
                *reinterpret_cast<uint4*>(Bl + off) =
                    *reinterpret_cast<const uint4*>(wl + go);
            }
            __syncthreads();
            uint32_t aBase = kc * 34816;
            #pragma unroll
            for (int term = 0; term < 3; term++) {
                uint32_t sA = ((term == 2) ? sAl : sAh) + aBase;
                uint32_t sB = (term == 1) ? sBl : sBh;
                #pragma unroll
                for (int ks = 0; ks < 8; ks++) {
                    uint32_t af[2][4];
                    #pragma unroll
                    for (int mi = 0; mi < 2; mi++)
                        ldmA(af[mi], sA + ((aRow + mi*16)*PIT + aKb + ks*16)*2);
                    #pragma unroll
                    for (int jj = 0; jj < 4; jj++) {
                        uint32_t bq4[4];
                        ldmB4(bq4, sB + ((bRow4 + jj*16)*PIT + bK4 + ks*16)*2);
                        #pragma unroll
                        for (int mi = 0; mi < 2; mi++) {
                            mma16816(acc[mi][2*jj],     af[mi], bq4);
                            mma16816(acc[mi][2*jj + 1], af[mi], bq4 + 2);
                        }
                    }
                }
            }
        }

        const float* bp = (wsel == 0) ? bq : (wsel == 1) ? bk : bv;
        float bias2[8][2];
        #pragma unroll
        for (int j = 0; j < 8; j++) {
            int c = wn*64 + j*8 + (lane & 3)*2;
            bias2[j][0] = bp[c]; bias2[j][1] = bp[c+1];
        }

        if (wsel < 2) {
            const float s = (wsel == 0) ? 0.0625f : 1.0f;
            __nv_bfloat16* gh = (wsel == 0) ? g_Qh : g_Kh;
            __nv_bfloat16* gl = (wsel == 0) ? g_Ql : g_Kl;
            #pragma unroll
            for (int mi = 0; mi < 2; mi++)
                #pragma unroll
                for (int j = 0; j < 8; j++) {
                    int r = wm*32 + mi*16 + (lane >> 2);
                    int c = wn*64 + j*8 + (lane & 3)*2;
                    float q0 = (acc[mi][j][0] + bias2[j][0]) * s;
                    float q1 = (acc[mi][j][1] + bias2[j][1]) * s;
                    float q2 = (acc[mi][j][2] + bias2[j][0]) * s;
                    float q3 = (acc[mi][j][3] + bias2[j][1]) * s;
                    size_t o0 = ((size_t)(b*Mm + m0 + r))*DOUT + c;
                    size_t o1 = ((size_t)(b*Mm + m0 + r + 8))*DOUT + c;
                    *reinterpret_cast<uint32_t*>(gh + o0) = b2pack(q0, q1);
                    *reinterpret_cast<uint32_t*>(gl + o0) =
                        b2pack(q0 - bhi(q0), q1 - bhi(q1));
                    *reinterpret_cast<uint32_t*>(gh + o1) = b2pack(q2, q3);
                    *reinterpret_cast<uint32_t*>(gl + o1) =
                        b2pack(q2 - bhi(q2), q3 - bhi(q3));
                }
        } else {
            __syncthreads();
            #pragma unroll
            for (int mi = 0; mi < 2; mi++)
                #pragma unroll
                for (int j = 0; j < 8; j++) {
                    int r = wm*32 + mi*16 + (lane >> 2);
                    int c = wn*64 + j*8 + (lane & 3)*2;
                    float v0 = fmaxf(acc[mi][j][0] + bias2[j][0], 0.f);
                    float v1 = fmaxf(acc[mi][j][1] + bias2[j][1], 0.f);
                    float v2 = fmaxf(acc[mi][j][2] + bias2[j][0], 0.f);
                    float v3 = fmaxf(acc[mi][j][3] + bias2[j][1], 0.f);
                    *reinterpret_cast<float2*>(
                        g_V + ((size_t)(b*Mm + m0 + r))*DOUT + c) = make_float2(v0, v1);
                    *reinterpret_cast<float2*>(
                        g_V + ((size_t)(b*Mm + m0 + r + 8))*DOUT + c) = make_float2(v2, v3);
                    Vs[r*132 + c]       = v0;
                    Vs[r*132 + c + 1]   = v1;
                    Vs[(r+8)*132 + c]   = v2;
                    Vs[(r+8)*132 + c+1] = v3;
                }
            __syncthreads();
            int e = tid & 127, half = tid >> 7;
            #pragma unroll
            for (int seg = 0; seg < 2; seg++) {
                int mb = half*64 + seg*32;
                uint32_t hp[16], lp[16];
                #pragma unroll
                for (int t = 0; t < 16; t++) {
                    float x0 = Vs[(mb + 2*t    )*132 + e];
                    float x1 = Vs[(mb + 2*t + 1)*132 + e];
                    hp[t] = b2pack(x0, x1);
                    lp[t] = b2pack(x0 - bhi(x0), x1 - bhi(x1));
                }
                uint4* dh = reinterpret_cast<uint4*>(
                    g_Vth + ((size_t)b*DOUT + e)*Mm + m0 + mb);
                uint4* dl = reinterpret_cast<uint4*>(
                    g_Vtl + ((size_t)b*DOUT + e)*Mm + m0 + mb);
                #pragma unroll
                for (int q = 0; q < 4; q++) {
                    dh[q] = make_uint4(hp[4*q],hp[4*q+1],hp[4*q+2],hp[4*q+3]);
                    dl[q] = make_uint4(lp[4*q],lp[4*q+1],lp[4*q+2],lp[4*q+3]);
                }
            }
        }
    }
}

// ---------------------------------------------------------------------------
// attnF: fused attention, split-K. 512 threads, 16 warps (8m x 2n).
// Warp (wm,wn): rows wm*16..+16, keys wn*32..+32 of each 64-key chunk.
// End: av halves combined in smem, rsum halves summed, then epilogue.
// smem: Qh|Ql 69632 + 2 stages x 71680 = 212992.
// ---------------------------------------------------------------------------
__global__ __launch_bounds__(512, 1)
void attnF_kernel(float* __restrict__ att, float* __restrict__ out)
{
    extern __shared__ char smraw[];
    const int tid = threadIdx.x, lane = tid & 31, wid = tid >> 5;
    const int b = blockIdx.y, m0 = blockIdx.x * 128;
    const int wm = wid >> 1, wn = wid & 1;

    char* Qh = smraw;
    char* Ql = smraw + 34816;
    const uint32_t sQh = cvta_smem(Qh), sQl = cvta_smem(Ql);
    const uint32_t sStg = cvta_smem(smraw + 69632);

    auto issue = [&](int ch, int st) {
        const uint32_t kb = sStg + st*71680;
        #pragma unroll
        for (int t = 0; t < 4; t++) {       // K: 2 tiles x 64 rows x 16 p
            int i = tid + t*512;
            int tile = i >> 10, row = (i >> 4) & 63, p = i & 15;
            const __nv_bfloat16* src = (tile ? g_Kl : g_Kh)
                + ((size_t)(b*Mm + ch*64 + row))*DOUT + p*8;
            CPA(kb + tile*17408 + row*PITB + p*16, src);
        }
        const uint32_t vb = kb + 34816;
        #pragma unroll
        for (int t = 0; t < 4; t++) {       // Vt: 2 tiles x 128 rows x 8 p
            int i = tid + t*512;
            int tile = i >> 10, row = (i >> 3) & 127, p = i & 7;
            const __nv_bfloat16* src = (tile ? g_Vtl : g_Vth)
                + ((size_t)(b*DOUT + row))*Mm + ch*64 + p*8;
            CPA(vb + tile*18432 + row*P64B + p*16, src);
        }
        CPC();
    };

    issue(0, 0);

    {   // Q resident (hi/lo), pitch 272
        const uint4* qh = reinterpret_cast<const uint4*>(g_Qh + ((size_t)b*Mm + m0)*DOUT);
        const uint4* ql = reinterpret_cast<const uint4*>(g_Ql + ((size_t)b*Mm + m0)*DOUT);
        for (int i = tid; i < 128*16; i += 512) {
            int row = i >> 4, c8 = i & 15;
            *reinterpret_cast<uint4*>(Qh + row*PITB + c8*16) = qh[i];
            *reinterpret_cast<uint4*>(Ql + row*PITB + c8*16) = ql[i];
        }
    }

    const int aRow  = wm*16 + (lane & 15);
    const int aKb   = (lane >> 4) * 8;
    const int bRowK = wn*32 + ((lane >> 4) << 3) + (lane & 7);   // key rows (S phase)
    const int bRowV = ((lane >> 4) << 3) + (lane & 7);           // dout rows (AV phase)
    const int bK4   = ((lane >> 3) & 1) * 8;

    float av[16][4] = {};
    float rsumA = 0.f, rsumB = 0.f;
    const int rloc = lane >> 2;

    #pragma unroll 1
    for (int ch = 0; ch < 32; ch++) {
        int st = ch & 1;
        if (ch < 31) issue(ch + 1, st ^ 1);
        if (ch < 31) { CPW1(); } else { CPW0(); }
        __syncthreads();

        const uint32_t kh = sStg + st*71680;
        const uint32_t kl = kh + 17408;
        const uint32_t vh = kh + 34816;
        const uint32_t vl = kh + 53248;

        // ---- S = Q K^T (3-term split), warp tile 16 x 32 ----
        float s[4][4] = {};
        #pragma unroll
        for (int term = 0; term < 3; term++) {
            uint32_t sA = (term == 2) ? sQl : sQh;
            uint32_t sB = (term == 1) ? kl : kh;
            #pragma unroll
            for (int kt = 0; kt < 8; kt++) {
                uint32_t af[4];
                ldmA(af, sA + (aRow*PIT + aKb + kt*16)*2);
                #pragma unroll
                for (int jj = 0; jj < 2; jj++) {
                    uint32_t bq4[4];
                    ldmB4(bq4, sB + (bRowK + jj*16)*PITB + (bK4 + kt*16)*2);
                    mma16816(s[2*jj],     af, bq4);
                    mma16816(s[2*jj + 1], af, bq4 + 2);
                }
            }
        }

        // ---- exp + partial row sums ----
        float psA = 0.f, psB = 0.f;
        #pragma unroll
        for (int j = 0; j < 4; j++) {
            s[j][0] = __expf(fminf(s[j][0], 80.f));
            s[j][1] = __expf(fminf(s[j][1], 80.f));
            s[j][2] = __expf(fminf(s[j][2], 80.f));
            s[j][3] = __expf(fminf(s[j][3], 80.f));
            psA += s[j][0] + s[j][1];
            psB += s[j][2] + s[j][3];
        }
        psA += __shfl_xor_sync(0xffffffffu, psA, 1);
        psA += __shfl_xor_sync(0xffffffffu, psA, 2);
        psB += __shfl_xor_sync(0xffffffffu, psB, 1);
        psB += __shfl_xor_sync(0xffffffffu, psB, 2);
        rsumA += psA;
        rsumB += psB;

        // ---- store unnormalized exp to this warp's key slice ----
        {
            float* a0 = att + ((size_t)(b*Mm + m0 + wm*16 + rloc))*Mm
                            + ch*64 + wn*32 + (lane & 3)*2;
            float* a1 = a0 + (size_t)8*Mm;
            #pragma unroll
            for (int j = 0; j < 4; j++) {
                *reinterpret_cast<float2*>(a0 + j*8) = make_float2(s[j][0], s[j][1]);
                *reinterpret_cast<float2*>(a1 + j*8) = make_float2(s[j][2], s[j][3]);
            }
        }

        // ---- AV += P @ V^T over this warp's 32 keys ----
        #pragma unroll
        for (int kt = 0; kt < 2; kt++) {
            const int j0 = 2*kt, j1 = 2*kt + 1;
            uint32_t afh[4], afl[4];
            afh[0] = b2pack(s[j0][0], s[j0][1]);
            afh[1] = b2pack(s[j0][2], s[j0][3]);
            afh[2] = b2pack(s[j1][0], s[j1][1]);
            afh[3] = b2pack(s[j1][2], s[j1][3]);
            afl[0] = b2pack(s[j0][0]-bhi(s[j0][0]), s[j0][1]-bhi(s[j0][1]));
            afl[1] = b2pack(s[j0][2]-bhi(s[j0][2]), s[j0][3]-bhi(s[j0][3]));
            afl[2] = b2pack(s[j1][0]-bhi(s[j1][0]), s[j1][1]-bhi(s[j1][1]));
            afl[3] = b2pack(s[j1][2]-bhi(s[j1][2]), s[j1][3]-bhi(s[j1][3]));
            const uint32_t ko = (wn*32 + kt*16 + bK4) * 2;
            #pragma unroll
            for (int jj = 0; jj < 8; jj++) {
                uint32_t bh4[4], bl4[4];
                ldmB4(bh4, vh + (bRowV + jj*16)*P64B + ko);
                ldmB4(bl4, vl + (bRowV + jj*16)*P64B + ko);
                mma16816(av[2*jj],     afh, bh4);
                mma16816(av[2*jj + 1], afh, bh4 + 2);
                mma16816(av[2*jj],     afh, bl4);
                mma16816(av[2*jj + 1], afh, bl4 + 2);
                mma16816(av[2*jj],     afl, bh4);
                mma16816(av[2*jj + 1], afl, bh4 + 2);
            }
        }
        __syncthreads();
    }

    // ---- combine av halves + rsum halves in smem ----
    float* Ss    = reinterpret_cast<float*>(smraw);        // 128 x 132
    float* rsumS = reinterpret_cast<float*>(smraw + 67584); // [2][128]
    if ((lane & 3) == 0) {
        rsumS[wn*128 + wm*16 + rloc]     = rsumA;
        rsumS[wn*128 + wm*16 + rloc + 8] = rsumB;
    }
    if (wn == 0) {
        #pragma unroll
        for (int jn = 0; jn < 16; jn++) {
            int r = wm*16 + rloc, c = jn*8 + (lane & 3)*2;
            Ss[r*132 + c]       = av[jn][0];
            Ss[r*132 + c + 1]   = av[jn][1];
            Ss[(r+8)*132 + c]   = av[jn][2];
            Ss[(r+8)*132 + c+1] = av[jn][3];
        }
    }
    __syncthreads();
    if (wn == 1) {
        #pragma unroll
        for (int jn = 0; jn < 16; jn++) {
            int r = wm*16 + rloc, c = jn*8 + (lane & 3)*2;
            Ss[r*132 + c]       += av[jn][0];
            Ss[r*132 + c + 1]   += av[jn][1];
            Ss[(r+8)*132 + c]   += av[jn][2];
            Ss[(r+8)*132 + c+1] += av[jn][3];
        }
    }
    __syncthreads();

    // ---- epilogue: all 16 warps, 8 rows each ----
    #pragma unroll 1
    for (int rr = 0; rr < 8; rr++) {
        int r = wid*8 + rr;
        float inv = 1.f / (rsumS[r] + rsumS[128 + r]);
        float a0 = Ss[r*132 + lane]      * inv, a1 = Ss[r*132 + lane + 32] * inv;
        float a2 = Ss[r*132 + lane + 64] * inv, a3 = Ss[r*132 + lane + 96] * inv;
        float ss = a0*a0 + a1*a1 + a2*a2 + a3*a3;
        #pragma unroll
        for (int o = 16; o > 0; o >>= 1) ss += __shfl_xor_sync(0xffffffffu, ss, o);
        float inv1 = rsqrtf(fmaxf(ss, 1e-12f));
        const float* vrow = g_V + ((size_t)b*Mm + m0 + r)*DOUT;
        float t0 = vrow[lane]      + a0*inv1;
        float t1 = vrow[lane + 32] + a1*inv1;
        float t2 = vrow[lane + 64] + a2*inv1;
        float t3 = vrow[lane + 96] + a3*inv1;
        float ss2 = t0*t0 + t1*t1 + t2*t2 + t3*t3;
        #pragma unroll
        for (int o = 16; o > 0; o >>= 1) ss2 += __shfl_xor_sync(0xffffffffu, ss2, o);
        float inv2 = rsqrtf(fmaxf(ss2, 1e-12f));
        float* orow = out + ((size_t)b*Mm + m0 + r)*DOUT;
        orow[lane]      = t0*inv2;
        orow[lane + 32] = t1*inv2;
        orow[lane + 64] = t2*inv2;
        orow[lane + 96] = t3*inv2;
    }

    // ---- pass 2: normalize att in place (16 warps x 8 rows) ----
    #pragma unroll 1
    for (int rr = 0; rr < 8; rr++) {
        int row = wid*8 + rr;
        float inv = 1.f / (rsumS[row] + rsumS[128 + row]);
        float4* ar = reinterpret_cast<float4*>(att + ((size_t)(b*Mm + m0 + row))*Mm);
        #pragma unroll
        for (int q = 0; q < 16; q++) {
            float4 v = ar[lane + q*32];
            v.x *= inv; v.y *= inv; v.z *= inv; v.w *= inv;
            ar[lane + q*32] = v;
        }
    }
}

// ---------------------------------------------------------------------------
extern "C" void kernel_launch(void* const* d_in, const int* in_sizes, int n_in,
                              void* d_out, int out_size)
{
    const float* Y   = (const float*)d_in[0];
    const int*   idx = (const int*)  d_in[1];
    const float* Wq  = (const float*)d_in[2];
    const float* bq  = (const float*)d_in[3];
    const float* Wk  = (const float*)d_in[4];
    const float* bk  = (const float*)d_in[5];
    const float* Wv  = (const float*)d_in[6];
    const float* bv  = (const float*)d_in[7];

    float* out = (float*)d_out;                       // [8,2048,128]
    float* att = out + (size_t)Bb*Mm*DOUT;            // [8,2048,2048]

    const int smemP = 208896;
    const int smemF = 212992;

    cudaFuncSetAttribute(projmma_kernel, cudaFuncAttributeMaxDynamicSharedMemorySize, smemP);
    cudaFuncSetAttribute(attnF_kernel,   cudaFuncAttributeMaxDynamicSharedMemorySize, smemF);

    prep_kernel<<<48, 256>>>(Wq, Wk, Wv);
    projmma_kernel<<<(Bb*Mm)/128, 256, smemP>>>(Y, idx, bq, bk, bv);
    attnF_kernel<<<dim3(Mm/128, Bb), 512, smemF>>>(att, out);
}

// round 15
// speedup vs baseline: 1.3429x; 1.3429x over previous
#include <cuda_runtime.h>
#include <cuda_bf16.h>
#include <cstdint>

#define Bb   8
#define Nn   4096
#define Mm   2048
#define DIN  256
#define DOUT 128

__device__ __nv_bfloat16 g_Qh [Bb*Mm*DOUT];
__device__ __nv_bfloat16 g_Ql [Bb*Mm*DOUT];
__device__ __nv_bfloat16 g_Kh [Bb*Mm*DOUT];
__device__ __nv_bfloat16 g_Kl [Bb*Mm*DOUT];
__device__ float         g_V  [Bb*Mm*DOUT];
__device__ __nv_bfloat16 g_Vth[Bb*DOUT*Mm];    // [b][e][m]
__device__ __nv_bfloat16 g_Vtl[Bb*DOUT*Mm];
__device__ __nv_bfloat16 g_Wth[3*DOUT*DIN];    // [wsel][n][k]
__device__ __nv_bfloat16 g_Wtl[3*DOUT*DIN];

// ---------------- helpers ----------------
__device__ __forceinline__ uint32_t cvta_smem(const void* p) {
    uint32_t a;
    asm("{ .reg .u64 t; cvta.to.shared.u64 t, %1; cvt.u32.u64 %0, t; }" : "=r"(a) : "l"(p));
    return a;
}
__device__ __forceinline__ uint32_t b2pack(float a, float b) {
    uint16_t la = __bfloat16_as_ushort(__float2bfloat16(a));
    uint16_t lb = __bfloat16_as_ushort(__float2bfloat16(b));
    return (uint32_t)la | ((uint32_t)lb << 16);
}
__device__ __forceinline__ float bhi(float x) {
    return __bfloat162float(__float2bfloat16(x));
}
__device__ __forceinline__ void ldmA(uint32_t a[4], uint32_t addr) {
    asm volatile("ldmatrix.sync.aligned.m8n8.x4.shared.b16 {%0,%1,%2,%3}, [%4];"
        : "=r"(a[0]),"=r"(a[1]),"=r"(a[2]),"=r"(a[3]) : "r"(addr));
}
__device__ __forceinline__ void ldmB4(uint32_t b[4], uint32_t addr) {
    asm volatile("ldmatrix.sync.aligned.m8n8.x4.shared.b16 {%0,%1,%2,%3}, [%4];"
        : "=r"(b[0]),"=r"(b[1]),"=r"(b[2]),"=r"(b[3]) : "r"(addr));
}
__device__ __forceinline__ void mma16816(float c[4], const uint32_t a[4], const uint32_t b[2]) {
    asm volatile("mma.sync.aligned.m16n8k16.row.col.f32.bf16.bf16.f32 "
        "{%0,%1,%2,%3}, {%4,%5,%6,%7}, {%8,%9}, {%0,%1,%2,%3};"
        : "+f"(c[0]),"+f"(c[1]),"+f"(c[2]),"+f"(c[3])
        : "r"(a[0]),"r"(a[1]),"r"(a[2]),"r"(a[3]), "r"(b[0]),"r"(b[1]));
}
#define CPA(d, s) asm volatile("cp.async.cg.shared.global [%0], [%1], 16;" :: "r"(d), "l"(s))
#define CPC()     asm volatile("cp.async.commit_group;" ::: "memory")
#define CPW1()    asm volatile("cp.async.wait_group 1;" ::: "memory")
#define CPW0()    asm volatile("cp.async.wait_group 0;" ::: "memory")

#define PIT 136
#define PITB 272
#define P64B 144

// ---------------------------------------------------------------------------
// prep: 48 blocks (round-13 proven).
// ---------------------------------------------------------------------------
__global__ void prep_kernel(const float* __restrict__ Wq,
                            const float* __restrict__ Wk,
                            const float* __restrict__ Wv)
{
    const int wsel  = blockIdx.x >> 4;
    const int slice = blockIdx.x & 15;
    const float* W = (wsel == 0) ? Wq : (wsel == 1) ? Wk : Wv;
    __nv_bfloat16* dh = g_Wth + wsel * DOUT * DIN;
    __nv_bfloat16* dl = g_Wtl + wsel * DOUT * DIN;
    const int n0 = slice * 8;
    for (int i = threadIdx.x; i < 8 * (DIN/2); i += 256) {
        int n = n0 + (i >> 7), k = (i & 127) * 2;
        float x0 = W[(size_t)k*DOUT + n];
        float x1 = W[(size_t)(k+1)*DOUT + n];
        *reinterpret_cast<uint32_t*>(dh + (size_t)n*DIN + k) = b2pack(x0, x1);
        *reinterpret_cast<uint32_t*>(dl + (size_t)n*DIN + k) =
            b2pack(x0 - bhi(x0), x1 - bhi(x1));
    }
}

// ---------------------------------------------------------------------------
// projmma: 256 threads, 8 warps (4m x 2n), warp tile 32x64.
// NEW: B tiles double-buffered via cp.async over 12 segments of k=64.
// smem: Ah 69632 | Al 69632 | 2 x Bstage 36864 (Bh 18432|Bl 18432) = 212992.
// ---------------------------------------------------------------------------
__global__ __launch_bounds__(256, 1)
void projmma_kernel(const float* __restrict__ Y, const int* __restrict__ idx,
                    const float* __restrict__ bq, const float* __restrict__ bk,
                    const float* __restrict__ bv)
{
    extern __shared__ char smraw[];
    char* Ah  = smraw;                       // 2 k-chunks x 34816
    char* Al  = smraw + 69632;
    char* Bst = smraw + 139264;              // 2 stages x 36864
    float* Vs = reinterpret_cast<float*>(Bst);  // phase-separated (wsel==2 tail)
    __shared__ int idxs[128];

    const int tid = threadIdx.x, lane = tid & 31, wid = tid >> 5;
    const int wm = wid >> 1, wn = wid & 1;
    const int row0 = blockIdx.x * 128;
    const int b    = row0 / Mm;
    const int m0   = row0 % Mm;

    const uint32_t sAh = cvta_smem(Ah), sAl = cvta_smem(Al);
    const uint32_t sB  = cvta_smem(Bst);

    // async B-segment fill: segment = wsel*4 + kc4 (k-chunk of 64)
    auto issueB = [&](int seg, int st) {
        const int wsel = seg >> 2, kc4 = seg & 3;
        const __nv_bfloat16* wh = g_Wth + (size_t)wsel*DOUT*DIN + kc4*64;
        const __nv_bfloat16* wl = g_Wtl + (size_t)wsel*DOUT*DIN + kc4*64;
        const uint32_t dbase = sB + st*36864;
        #pragma unroll
        for (int t = 0; t < 8; t++) {
            int i = tid + t*256;
            int tile = i >> 10, row = (i >> 3) & 127, p = i & 7;
            const __nv_bfloat16* src = (tile ? wl : wh) + (size_t)row*DIN + p*8;
            CPA(dbase + tile*18432 + row*P64B + p*16, src);
        }
        CPC();
    };

    issueB(0, 0);

    if (tid < 128) idxs[tid] = idx[b*Mm + m0 + tid];
    __syncthreads();

    // gather + split A: Y rows fp32 -> bf16 hi/lo, two 128-k chunks
    for (int i = tid; i < 128*64; i += 256) {
        int row = i >> 6, c4 = i & 63;
        float4 y = *reinterpret_cast<const float4*>(
            Y + ((size_t)b*Nn + idxs[row])*DIN + c4*4);
        int kc = c4 >> 5;
        uint32_t off = (uint32_t)(kc*34816 + row*PITB + (c4 & 31)*8);
        *reinterpret_cast<uint2*>(Ah + off) =
            make_uint2(b2pack(y.x, y.y), b2pack(y.z, y.w));
        *reinterpret_cast<uint2*>(Al + off) =
            make_uint2(b2pack(y.x-bhi(y.x), y.y-bhi(y.y)),
                       b2pack(y.z-bhi(y.z), y.w-bhi(y.w)));
    }

    const int aRow  = wm*32 + (lane & 15);
    const int aKb   = (lane >> 4) * 8;
    const int bRow4 = wn*64 + ((lane >> 4) << 3) + (lane & 7);
    const int bK4   = ((lane >> 3) & 1) * 8;

    float acc[2][8][4] = {};

    #pragma unroll 1
    for (int seg = 0; seg < 12; seg++) {
        const int wsel = seg >> 2, kc4 = seg & 3;
        const int st = seg & 1;
        if (seg < 11) issueB(seg + 1, st ^ 1);
        if (seg < 11) { CPW1(); } else { CPW0(); }
        __syncthreads();   // B stage ready (+ gather visible on seg 0)

        const uint32_t tBh = sB + st*36864, tBl = tBh + 18432;
        const uint32_t aCh = (uint32_t)((kc4 >> 1) * 34816);
        const int      kIn = (kc4 & 1) * 64;

        #pragma unroll
        for (int term = 0; term < 3; term++) {
            uint32_t sA = ((term == 2) ? sAl : sAh) + aCh;
            uint32_t sBt = (term == 1) ? tBl : tBh;
            #pragma unroll
            for (int ks = 0; ks < 4; ks++) {
                uint32_t af[2][4];
                #pragma unroll
                for (int mi = 0; mi < 2; mi++)
                    ldmA(af[mi], sA + ((aRow + mi*16)*PIT + kIn + aKb + ks*16)*2);
                #pragma unroll
                for (int jj = 0; jj < 4; jj++) {
                    uint32_t bq4[4];
                    ldmB4(bq4, sBt + (bRow4 + jj*16)*P64B + (bK4 + ks*16)*2);
                    #pragma unroll
                    for (int mi = 0; mi < 2; mi++) {
                        mma16816(acc[mi][2*jj],     af[mi], bq4);
                        mma16816(acc[mi][2*jj + 1], af[mi], bq4 + 2);
                    }
                }
            }
        }
        __syncthreads();   // stage fully consumed before it is re-issued

        if (kc4 == 3) {
            // ---- epilogue for this weight ----
            const float* bp = (wsel == 0) ? bq : (wsel == 1) ? bk : bv;
            float bias2[8][2];
            #pragma unroll
            for (int j = 0; j < 8; j++) {
                int c = wn*64 + j*8 + (lane & 3)*2;
                bias2[j][0] = bp[c]; bias2[j][1] = bp[c+1];
            }

            if (wsel < 2) {
                const float s = (wsel == 0) ? 0.0625f : 1.0f;
                __nv_bfloat16* gh = (wsel == 0) ? g_Qh : g_Kh;
                __nv_bfloat16* gl = (wsel == 0) ? g_Ql : g_Kl;
                #pragma unroll
                for (int mi = 0; mi < 2; mi++)
                    #pragma unroll
                    for (int j = 0; j < 8; j++) {
                        int r = wm*32 + mi*16 + (lane >> 2);
                        int c = wn*64 + j*8 + (lane & 3)*2;
                        float q0 = (acc[mi][j][0] + bias2[j][0]) * s;
                        float q1 = (acc[mi][j][1] + bias2[j][1]) * s;
                        float q2 = (acc[mi][j][2] + bias2[j][0]) * s;
                        float q3 = (acc[mi][j][3] + bias2[j][1]) * s;
                        size_t o0 = ((size_t)(b*Mm + m0 + r))*DOUT + c;
                        size_t o1 = ((size_t)(b*Mm + m0 + r + 8))*DOUT + c;
                        *reinterpret_cast<uint32_t*>(gh + o0) = b2pack(q0, q1);
                        *reinterpret_cast<uint32_t*>(gl + o0) =
                            b2pack(q0 - bhi(q0), q1 - bhi(q1));
                        *reinterpret_cast<uint32_t*>(gh + o1) = b2pack(q2, q3);
                        *reinterpret_cast<uint32_t*>(gl + o1) =
                            b2pack(q2 - bhi(q2), q3 - bhi(q3));
                    }
            } else {
                // V: relu, fp32 store + smem transpose (Vs aliases B stages;
                // seg==11 is last, no pending cp.async, all reads barriered).
                #pragma unroll
                for (int mi = 0; mi < 2; mi++)
                    #pragma unroll
                    for (int j = 0; j < 8; j++) {
                        int r = wm*32 + mi*16 + (lane >> 2);
                        int c = wn*64 + j*8 + (lane & 3)*2;
                        float v0 = fmaxf(acc[mi][j][0] + bias2[j][0], 0.f);
                        float v1 = fmaxf(acc[mi][j][1] + bias2[j][1], 0.f);
                        float v2 = fmaxf(acc[mi][j][2] + bias2[j][0], 0.f);
                        float v3 = fmaxf(acc[mi][j][3] + bias2[j][1], 0.f);
                        *reinterpret_cast<float2*>(
                            g_V + ((size_t)(b*Mm + m0 + r))*DOUT + c) = make_float2(v0, v1);
                        *reinterpret_cast<float2*>(
                            g_V + ((size_t)(b*Mm + m0 + r + 8))*DOUT + c) = make_float2(v2, v3);
                        Vs[r*132 + c]       = v0;
                        Vs[r*132 + c + 1]   = v1;
                        Vs[(r+8)*132 + c]   = v2;
                        Vs[(r+8)*132 + c+1] = v3;
                    }
                __syncthreads();
                int e = tid & 127, half = tid >> 7;
                #pragma unroll
                for (int seg2 = 0; seg2 < 2; seg2++) {
                    int mb = half*64 + seg2*32;
                    uint32_t hp[16], lp[16];
                    #pragma unroll
                    for (int t = 0; t < 16; t++) {
                        float x0 = Vs[(mb + 2*t    )*132 + e];
                        float x1 = Vs[(mb + 2*t + 1)*132 + e];
                        hp[t] = b2pack(x0, x1);
                        lp[t] = b2pack(x0 - bhi(x0), x1 - bhi(x1));
                    }
                    uint4* dh = reinterpret_cast<uint4*>(
                        g_Vth + ((size_t)b*DOUT + e)*Mm + m0 + mb);
                    uint4* dl = reinterpret_cast<uint4*>(
                        g_Vtl + ((size_t)b*DOUT + e)*Mm + m0 + mb);
                    #pragma unroll
                    for (int q = 0; q < 4; q++) {
                        dh[q] = make_uint4(hp[4*q],hp[4*q+1],hp[4*q+2],hp[4*q+3]);
                        dl[q] = make_uint4(lp[4*q],lp[4*q+1],lp[4*q+2],lp[4*q+3]);
                    }
                }
            }
            // reset accumulators for next weight
            #pragma unroll
            for (int mi = 0; mi < 2; mi++)
                #pragma unroll
                for (int j = 0; j < 8; j++) {
                    acc[mi][j][0] = 0.f; acc[mi][j][1] = 0.f;
                    acc[mi][j][2] = 0.f; acc[mi][j][3] = 0.f;
                }
        }
    }
}

// ---------------------------------------------------------------------------
// attnF: FUSED QK^T + softmax + AV + l2norm (round-12/13 proven, verbatim).
// ---------------------------------------------------------------------------
__global__ __launch_bounds__(256, 1)
void attnF_kernel(float* __restrict__ att, float* __restrict__ out)
{
    extern __shared__ char smraw[];
    const int tid = threadIdx.x, lane = tid & 31, wid = tid >> 5;
    const int b = blockIdx.y, m0 = blockIdx.x * 128;

    char* Qh = smraw;
    char* Ql = smraw + 34816;
    const uint32_t sQh = cvta_smem(Qh), sQl = cvta_smem(Ql);
    const uint32_t sStg = cvta_smem(smraw + 69632);

    auto issue = [&](int ch, int st) {
        const uint32_t kb = sStg + st*71680;
        #pragma unroll
        for (int t = 0; t < 8; t++) {
            int i = tid + t*256;
            int tile = i >> 10, row = (i >> 4) & 63, p = i & 15;
            const __nv_bfloat16* src = (tile ? g_Kl : g_Kh)
                + ((size_t)(b*Mm + ch*64 + row))*DOUT + p*8;
            CPA(kb + tile*17408 + row*PITB + p*16, src);
        }
        const uint32_t vb = kb + 34816;
        #pragma unroll
        for (int t = 0; t < 8; t++) {
            int i = tid + t*256;
            int tile = i >> 10, row = (i >> 3) & 127, p = i & 7;
            const __nv_bfloat16* src = (tile ? g_Vtl : g_Vth)
                + ((size_t)(b*DOUT + row))*Mm + ch*64 + p*8;
            CPA(vb + tile*18432 + row*P64B + p*16, src);
        }
        CPC();
    };

    issue(0, 0);

    {
        const uint4* qh = reinterpret_cast<const uint4*>(g_Qh + ((size_t)b*Mm + m0)*DOUT);
        const uint4* ql = reinterpret_cast<const uint4*>(g_Ql + ((size_t)b*Mm + m0)*DOUT);
        for (int i = tid; i < 128*16; i += 256) {
            int row = i >> 4, c8 = i & 15;
            *reinterpret_cast<uint4*>(Qh + row*PITB + c8*16) = qh[i];
            *reinterpret_cast<uint4*>(Ql + row*PITB + c8*16) = ql[i];
        }
    }

    const int aRow  = wid*16 + (lane & 15);
    const int aKb   = (lane >> 4) * 8;
    const int bRow4 = ((lane >> 4) << 3) + (lane & 7);
    const int bK4   = ((lane >> 3) & 1) * 8;

    float av[16][4] = {};
    float rsumA = 0.f, rsumB = 0.f;
    const int rloc = lane >> 2;

    #pragma unroll 1
    for (int ch = 0; ch < 32; ch++) {
        int st = ch & 1;
        if (ch < 31) issue(ch + 1, st ^ 1);
        if (ch < 31) { CPW1(); } else { CPW0(); }
        __syncthreads();

        const uint32_t kh = sStg + st*71680;
        const uint32_t kl = kh + 17408;
        const uint32_t vh = kh + 34816;
        const uint32_t vl = kh + 53248;

        float s[8][4] = {};
        #pragma unroll
        for (int term = 0; term < 3; term++) {
            uint32_t sA = (term == 2) ? sQl : sQh;
            uint32_t sB = (term == 1) ? kl : kh;
            #pragma unroll
            for (int kt = 0; kt < 8; kt++) {
                uint32_t af[4];
                ldmA(af, sA + (aRow*PIT + aKb + kt*16)*2);
                #pragma unroll
                for (int jj = 0; jj < 4; jj++) {
                    uint32_t bq4[4];
                    ldmB4(bq4, sB + (bRow4 + jj*16)*PITB + (bK4 + kt*16)*2);
                    mma16816(s[2*jj],     af, bq4);
                    mma16816(s[2*jj + 1], af, bq4 + 2);
                }
            }
        }

        float psA = 0.f, psB = 0.f;
        #pragma unroll
        for (int j = 0; j < 8; j++) {
            s[j][0] = __expf(fminf(s[j][0], 80.f));
            s[j][1] = __expf(fminf(s[j][1], 80.f));
            s[j][2] = __expf(fminf(s[j][2], 80.f));
            s[j][3] = __expf(fminf(s[j][3], 80.f));
            psA += s[j][0] + s[j][1];
            psB += s[j][2] + s[j][3];
        }
        psA += __shfl_xor_sync(0xffffffffu, psA, 1);
        psA += __shfl_xor_sync(0xffffffffu, psA, 2);
        psB += __shfl_xor_sync(0xffffffffu, psB, 1);
        psB += __shfl_xor_sync(0xffffffffu, psB, 2);
        rsumA += psA;
        rsumB += psB;

        {
            float* a0 = att + ((size_t)(b*Mm + m0 + wid*16 + rloc))*Mm
                            + ch*64 + (lane & 3)*2;
            float* a1 = a0 + (size_t)8*Mm;
            #pragma unroll
            for (int j = 0; j < 8; j++) {
                *reinterpret_cast<float2*>(a0 + j*8) = make_float2(s[j][0], s[j][1]);
                *reinterpret_cast<float2*>(a1 + j*8) = make_float2(s[j][2], s[j][3]);
            }
        }

        #pragma unroll
        for (int kt = 0; kt < 4; kt++) {
            const int j0 = 2*kt, j1 = 2*kt + 1;
            uint32_t afh[4], afl[4];
            afh[0] = b2pack(s[j0][0], s[j0][1]);
            afh[1] = b2pack(s[j0][2], s[j0][3]);
            afh[2] = b2pack(s[j1][0], s[j1][1]);
            afh[3] = b2pack(s[j1][2], s[j1][3]);
            afl[0] = b2pack(s[j0][0]-bhi(s[j0][0]), s[j0][1]-bhi(s[j0][1]));
            afl[1] = b2pack(s[j0][2]-bhi(s[j0][2]), s[j0][3]-bhi(s[j0][3]));
            afl[2] = b2pack(s[j1][0]-bhi(s[j1][0]), s[j1][1]-bhi(s[j1][1]));
            afl[3] = b2pack(s[j1][2]-bhi(s[j1][2]), s[j1][3]-bhi(s[j1][3]));
            #pragma unroll
            for (int jj = 0; jj < 8; jj++) {
                uint32_t bh4[4], bl4[4];
                ldmB4(bh4, vh + (bRow4 + jj*16)*P64B + (bK4 + kt*16)*2);
                ldmB4(bl4, vl + (bRow4 + jj*16)*P64B + (bK4 + kt*16)*2);
                mma16816(av[2*jj],     afh, bh4);
                mma16816(av[2*jj + 1], afh, bh4 + 2);
                mma16816(av[2*jj],     afh, bl4);
                mma16816(av[2*jj + 1], afh, bl4 + 2);
                mma16816(av[2*jj],     afl, bh4);
                mma16816(av[2*jj + 1], afl, bh4 + 2);
            }
        }
        __syncthreads();
    }

    float invA = 1.f / rsumA, invB = 1.f / rsumB;
    float ssA = 0.f, ssB = 0.f;
    #pragma unroll
    for (int jn = 0; jn < 16; jn++) {
        av[jn][0] *= invA; av[jn][1] *= invA;
        av[jn][2] *= invB; av[jn][3] *= invB;
        ssA += av[jn][0]*av[jn][0] + av[jn][1]*av[jn][1];
        ssB += av[jn][2]*av[jn][2] + av[jn][3]*av[jn][3];
    }
    ssA += __shfl_xor_sync(0xffffffffu, ssA, 1);
    ssA += __shfl_xor_sync(0xffffffffu, ssA, 2);
    ssB += __shfl_xor_sync(0xffffffffu, ssB, 1);
    ssB += __shfl_xor_sync(0xffffffffu, ssB, 2);
    float n1A = rsqrtf(fmaxf(ssA, 1e-12f));
    float n1B = rsqrtf(fmaxf(ssB, 1e-12f));

    const float* v0p = g_V + ((size_t)(b*Mm + m0 + wid*16 + rloc))*DOUT + (lane & 3)*2;
    const float* v1p = v0p + 8*DOUT;
    float ss2A = 0.f, ss2B = 0.f;
    #pragma unroll
    for (int jn = 0; jn < 16; jn++) {
        float2 v0 = *reinterpret_cast<const float2*>(v0p + jn*8);
        float2 v1 = *reinterpret_cast<const float2*>(v1p + jn*8);
        av[jn][0] = v0.x + av[jn][0]*n1A;
        av[jn][1] = v0.y + av[jn][1]*n1A;
        av[jn][2] = v1.x + av[jn][2]*n1B;
        av[jn][3] = v1.y + av[jn][3]*n1B;
        ss2A += av[jn][0]*av[jn][0] + av[jn][1]*av[jn][1];
        ss2B += av[jn][2]*av[jn][2] + av[jn][3]*av[jn][3];
    }
    ss2A += __shfl_xor_sync(0xffffffffu, ss2A, 1);
    ss2A += __shfl_xor_sync(0xffffffffu, ss2A, 2);
    ss2B += __shfl_xor_sync(0xffffffffu, ss2B, 1);
    ss2B += __shfl_xor_sync(0xffffffffu, ss2B, 2);
    float n2A = rsqrtf(fmaxf(ss2A, 1e-12f));
    float n2B = rsqrtf(fmaxf(ss2B, 1e-12f));

    {
        float* o0 = out + ((size_t)(b*Mm + m0 + wid*16 + rloc))*DOUT + (lane & 3)*2;
        float* o1 = o0 + 8*DOUT;
        #pragma unroll
        for (int jn = 0; jn < 16; jn++) {
            *reinterpret_cast<float2*>(o0 + jn*8) =
                make_float2(av[jn][0]*n2A, av[jn][1]*n2A);
            *reinterpret_cast<float2*>(o1 + jn*8) =
                make_float2(av[jn][2]*n2B, av[jn][3]*n2B);
        }
    }

    float* invS = reinterpret_cast<float*>(smraw);
    if ((lane & 3) == 0) {
        invS[wid*16 + rloc]     = invA;
        invS[wid*16 + rloc + 8] = invB;
    }
    __syncthreads();
    #pragma unroll 1
    for (int rr = 0; rr < 16; rr++) {
        int row = wid*16 + rr;
        float inv = invS[row];
        float4* ar = reinterpret_cast<float4*>(att + ((size_t)(b*Mm + m0 + row))*Mm);
        #pragma unroll
        for (int q = 0; q < 16; q++) {
            float4 v = ar[lane + q*32];
            v.x *= inv; v.y *= inv; v.z *= inv; v.w *= inv;
            ar[lane + q*32] = v;
        }
    }
}

// ---------------------------------------------------------------------------
extern "C" void kernel_launch(void* const* d_in, const int* in_sizes, int n_in,
                              void* d_out, int out_size)
{
    const float* Y   = (const float*)d_in[0];
    const int*   idx = (const int*)  d_in[1];
    const float* Wq  = (const float*)d_in[2];
    const float* bq  = (const float*)d_in[3];
    const float* Wk  = (const float*)d_in[4];
    const float* bk  = (const float*)d_in[5];
    const float* Wv  = (const float*)d_in[6];
    const float* bv  = (const float*)d_in[7];

    float* out = (float*)d_out;                       // [8,2048,128]
    float* att = out + (size_t)Bb*Mm*DOUT;            // [8,2048,2048]

    const int smemP = 212992;
    const int smemF = 212992;

    cudaFuncSetAttribute(projmma_kernel, cudaFuncAttributeMaxDynamicSharedMemorySize, smemP);
    cudaFuncSetAttribute(attnF_kernel,   cudaFuncAttributeMaxDynamicSharedMemorySize, smemF);

    prep_kernel<<<48, 256>>>(Wq, Wk, Wv);
    projmma_kernel<<<(Bb*Mm)/128, 256, smemP>>>(Y, idx, bq, bk, bv);
    attnF_kernel<<<dim3(Mm/128, Bb), 256, smemF>>>(att, out);
}